// round 2
// baseline (speedup 1.0000x reference)
#include <cuda_runtime.h>
#include <cuda_bf16.h>

#define N_NODES 50000
#define E_EDGES 500000
#define IN_CH   128
#define OUT_CH  256

// Scratch (allocation-free rule: __device__ globals)
__device__ __align__(16) float g_deg[N_NODES];
__device__ __align__(16) float g_dinv[N_NODES];
__device__ __align__(16) float g_h[(size_t)N_NODES * OUT_CH];
__device__ int g_is64;   // 1 if edge_index is int64, 0 if int32

__device__ __forceinline__ float sigmoidf_(float v) {
    return 1.0f / (1.0f + __expf(-v));
}

// Decode node index e of row (which=0) / col (which=1) under detected dtype.
__device__ __forceinline__ int load_idx(const void* ei, int E, int which, int e) {
    if (g_is64) {
        return (int)((const long long*)ei)[(size_t)which * E + e];
    } else {
        return ((const int*)ei)[which * E + e];
    }
}

// kD: detect edge_index dtype. int64 data (values < 2^31) has all odd int32
// words == 0; int32 data has random node ids there.
__global__ void detect_kernel(const int* __restrict__ ei32) {
    __shared__ int any_nonzero;
    if (threadIdx.x == 0) any_nonzero = 0;
    __syncthreads();
    for (int i = threadIdx.x; i < 1024; i += blockDim.x) {
        if (ei32[2 * i + 1] != 0) any_nonzero = 1;  // benign race
    }
    __syncthreads();
    if (threadIdx.x == 0) g_is64 = any_nonzero ? 0 : 1;
}

// k0: init degree to 1.0 (self-loop weight)
__global__ void deg_init_kernel(int n) {
    int i = blockIdx.x * blockDim.x + threadIdx.x;
    if (i < n) g_deg[i] = 1.0f;
}

// k1: accumulate sigmoid(edge_weight) into degree of target node
__global__ void deg_accum_kernel(const void* __restrict__ ei,
                                 const float* __restrict__ ew, int E) {
    int e = blockIdx.x * blockDim.x + threadIdx.x;
    if (e < E) {
        int c = load_idx(ei, E, 1, e);
        float w = sigmoidf_(ew[e]);
        atomicAdd(&g_deg[c], w);
    }
}

// k2: dinv = rsqrt(deg)   (deg >= 1 always: self-loop weight 1, sigmoid > 0)
__global__ void dinv_kernel(int n) {
    int i = blockIdx.x * blockDim.x + threadIdx.x;
    if (i < n) g_dinv[i] = rsqrtf(g_deg[i]);
}

// k3: SGEMM  h[M,256] = x[M,128] @ W[128,256]
// Block tile 64x64, K-step 16, 256 threads, 4x4 register tile per thread.
#define GM 64
#define GN 64
#define GK 16
__global__ __launch_bounds__(256) void gemm_kernel(const float* __restrict__ x,
                                                   const float* __restrict__ W,
                                                   int M) {
    __shared__ float As[GK][GM];       // transposed A tile: As[k][m]
    __shared__ float Bs[GK][GN];

    const int tid = threadIdx.x;
    const int tx = tid & 15;           // 0..15  -> N direction (x4)
    const int ty = tid >> 4;           // 0..15  -> M direction (x4)
    const int bm = blockIdx.y * GM;
    const int bn = blockIdx.x * GN;

    float acc[4][4];
    #pragma unroll
    for (int i = 0; i < 4; i++)
        #pragma unroll
        for (int j = 0; j < 4; j++) acc[i][j] = 0.0f;

    // A load mapping: 64 rows x 16 k => 1024 elems, 4/thread (one float4)
    const int ar = tid >> 2;           // 0..63
    const int ak = (tid & 3) * 4;      // 0,4,8,12
    // B load mapping: 16 k x 64 cols => 1024 elems, 4/thread (one float4)
    const int br = tid >> 4;           // 0..15
    const int bc = (tid & 15) * 4;     // 0..60

    for (int k0 = 0; k0 < IN_CH; k0 += GK) {
        const int grow = bm + ar;
        float4 av;
        if (grow < M) av = *(const float4*)&x[(size_t)grow * IN_CH + k0 + ak];
        else          av = make_float4(0.f, 0.f, 0.f, 0.f);
        As[ak + 0][ar] = av.x;
        As[ak + 1][ar] = av.y;
        As[ak + 2][ar] = av.z;
        As[ak + 3][ar] = av.w;

        *(float4*)&Bs[br][bc] = *(const float4*)&W[(size_t)(k0 + br) * OUT_CH + bn + bc];

        __syncthreads();

        #pragma unroll
        for (int k = 0; k < GK; k++) {
            float a0 = As[k][ty * 4 + 0];
            float a1 = As[k][ty * 4 + 1];
            float a2 = As[k][ty * 4 + 2];
            float a3 = As[k][ty * 4 + 3];
            float4 bv = *(const float4*)&Bs[k][tx * 4];
            acc[0][0] += a0 * bv.x; acc[0][1] += a0 * bv.y; acc[0][2] += a0 * bv.z; acc[0][3] += a0 * bv.w;
            acc[1][0] += a1 * bv.x; acc[1][1] += a1 * bv.y; acc[1][2] += a1 * bv.z; acc[1][3] += a1 * bv.w;
            acc[2][0] += a2 * bv.x; acc[2][1] += a2 * bv.y; acc[2][2] += a2 * bv.z; acc[2][3] += a2 * bv.w;
            acc[3][0] += a3 * bv.x; acc[3][1] += a3 * bv.y; acc[3][2] += a3 * bv.z; acc[3][3] += a3 * bv.w;
        }
        __syncthreads();
    }

    #pragma unroll
    for (int i = 0; i < 4; i++) {
        const int grow = bm + ty * 4 + i;
        if (grow < M) {
            float4 v = make_float4(acc[i][0], acc[i][1], acc[i][2], acc[i][3]);
            *(float4*)&g_h[(size_t)grow * OUT_CH + bn + tx * 4] = v;
        }
    }
}

// k4: out = b + h * dinv^2   (self-loop contribution: norm = dinv[i]*1*dinv[i])
__global__ void out_init_kernel(const float* __restrict__ b, float* __restrict__ out, int n) {
    const int node = blockIdx.x;
    const int c = threadIdx.x;
    if (node < n) {
        float d = g_dinv[node];
        float d2 = d * d;
        size_t idx = (size_t)node * OUT_CH + c;
        out[idx] = b[c] + g_h[idx] * d2;
    }
}

// k5: one warp per edge: out[col] += h[row] * (dinv[row]*sigmoid(w)*dinv[col])
// 256 floats per edge -> 2 float4 per lane, vector reductions (red.global.add.v4.f32)
__global__ __launch_bounds__(256) void scatter_kernel(const void* __restrict__ ei,
                                                      const float* __restrict__ ew,
                                                      float* __restrict__ out, int E) {
    const int gid = blockIdx.x * blockDim.x + threadIdx.x;
    const int e = gid >> 5;
    const int lane = gid & 31;
    if (e >= E) return;

    const int r = load_idx(ei, E, 0, e);
    const int c = load_idx(ei, E, 1, e);
    const float w = sigmoidf_(ew[e]);
    const float norm = g_dinv[r] * w * g_dinv[c];

    const float4* hv = (const float4*)(g_h + (size_t)r * OUT_CH);
    float* op = out + (size_t)c * OUT_CH;

    #pragma unroll
    for (int i = 0; i < 2; i++) {
        float4 v = hv[lane + i * 32];
        v.x *= norm; v.y *= norm; v.z *= norm; v.w *= norm;
        float* addr = op + (size_t)(lane + i * 32) * 4;
        asm volatile("red.global.add.v4.f32 [%0], {%1, %2, %3, %4};"
                     :: "l"(addr), "f"(v.x), "f"(v.y), "f"(v.z), "f"(v.w)
                     : "memory");
    }
}

extern "C" void kernel_launch(void* const* d_in, const int* in_sizes, int n_in,
                              void* d_out, int out_size) {
    const float* x   = (const float*)d_in[0];      // [N,128]
    const float* W   = (const float*)d_in[1];      // [128,256]
    const float* b   = (const float*)d_in[2];      // [256]
    const void*  ei  = d_in[3];                    // [2,E] int64 OR int32
    const float* ew  = (const float*)d_in[4];      // [E]

    const int N = in_sizes[0] / IN_CH;
    const int E = in_sizes[4];
    float* out = (float*)d_out;

    detect_kernel<<<1, 256>>>((const int*)ei);

    deg_init_kernel<<<(N + 255) / 256, 256>>>(N);
    deg_accum_kernel<<<(E + 255) / 256, 256>>>(ei, ew, E);
    dinv_kernel<<<(N + 255) / 256, 256>>>(N);

    dim3 ggrid(OUT_CH / GN, (N + GM - 1) / GM);
    gemm_kernel<<<ggrid, 256>>>(x, W, N);

    out_init_kernel<<<N, OUT_CH>>>(b, out, N);

    const long long nthreads = (long long)E * 32;
    scatter_kernel<<<(unsigned)((nthreads + 255) / 256), 256>>>(ei, ew, out, E);
}

// round 3
// speedup vs baseline: 1.5232x; 1.5232x over previous
#include <cuda_runtime.h>
#include <cuda_bf16.h>

#define N_NODES 50000
#define E_EDGES 500000
#define IN_CH   128
#define OUT_CH  256

// Scratch (allocation-free rule: __device__ globals)
__device__ __align__(16) float g_deg[N_NODES];
__device__ __align__(16) float g_dinv[N_NODES];
__device__ __align__(16) float g_y[(size_t)N_NODES * IN_CH];   // aggregated features (A_hat @ x)
__device__ int g_is64;   // 1 if edge_index is int64, 0 if int32

__device__ __forceinline__ float sigmoidf_(float v) {
    return 1.0f / (1.0f + __expf(-v));
}

__device__ __forceinline__ int load_idx(const void* ei, int E, int which, int e) {
    if (g_is64) return (int)((const long long*)ei)[(size_t)which * E + e];
    else        return ((const int*)ei)[which * E + e];
}

// kD: detect edge_index dtype. int64 (values < 2^31) -> all odd int32 words 0.
__global__ void detect_kernel(const int* __restrict__ ei32) {
    __shared__ int any_nonzero;
    if (threadIdx.x == 0) any_nonzero = 0;
    __syncthreads();
    for (int i = threadIdx.x; i < 1024; i += blockDim.x)
        if (ei32[2 * i + 1] != 0) any_nonzero = 1;   // benign race
    __syncthreads();
    if (threadIdx.x == 0) g_is64 = any_nonzero ? 0 : 1;
}

// k0: deg = 1.0 (self-loop weight)
__global__ void deg_init_kernel(int n) {
    int i = blockIdx.x * blockDim.x + threadIdx.x;
    if (i < n) g_deg[i] = 1.0f;
}

// k1: deg[col] += sigmoid(ew)
__global__ void deg_accum_kernel(const void* __restrict__ ei,
                                 const float* __restrict__ ew, int E) {
    int e = blockIdx.x * blockDim.x + threadIdx.x;
    if (e < E) {
        int c = load_idx(ei, E, 1, e);
        atomicAdd(&g_deg[c], sigmoidf_(ew[e]));
    }
}

// k2: dinv = rsqrt(deg)
__global__ void dinv_kernel(int n) {
    int i = blockIdx.x * blockDim.x + threadIdx.x;
    if (i < n) g_dinv[i] = rsqrtf(g_deg[i]);
}

// k3: y = x * dinv^2 (self-loop term of the aggregation), float4-vectorized
__global__ void agg_init_kernel(const float* __restrict__ x, int n) {
    int i = blockIdx.x * blockDim.x + threadIdx.x;   // one float4 per thread
    int total = n * (IN_CH / 4);
    if (i < total) {
        int node = i / (IN_CH / 4);
        float d = g_dinv[node];
        float d2 = d * d;
        float4 v = ((const float4*)x)[i];
        v.x *= d2; v.y *= d2; v.z *= d2; v.w *= d2;
        ((float4*)g_y)[i] = v;
    }
}

// k4: one warp per edge: y[col] += x[row] * (dinv[row]*sigmoid(w)*dinv[col])
// 128 floats per edge -> exactly 1 float4 per lane, vector RED.
__global__ __launch_bounds__(256) void agg_scatter_kernel(const void* __restrict__ ei,
                                                          const float* __restrict__ ew,
                                                          const float* __restrict__ x, int E) {
    const int gid = blockIdx.x * blockDim.x + threadIdx.x;
    const int e = gid >> 5;
    const int lane = gid & 31;
    if (e >= E) return;

    const int r = load_idx(ei, E, 0, e);
    const int c = load_idx(ei, E, 1, e);
    const float norm = g_dinv[r] * sigmoidf_(ew[e]) * g_dinv[c];

    float4 v = ((const float4*)(x + (size_t)r * IN_CH))[lane];
    v.x *= norm; v.y *= norm; v.z *= norm; v.w *= norm;
    float* addr = g_y + (size_t)c * IN_CH + lane * 4;
    asm volatile("red.global.add.v4.f32 [%0], {%1, %2, %3, %4};"
                 :: "l"(addr), "f"(v.x), "f"(v.y), "f"(v.z), "f"(v.w)
                 : "memory");
}

// k5: SGEMM  out[M,256] = y[M,128] @ W[128,256] + b
// 128x128 block tile, BK=8, 8x8 register tile, 256 threads.
#define BM 128
#define BN 128
#define BK 8
__global__ __launch_bounds__(256) void gemm_kernel(const float* __restrict__ W,
                                                   const float* __restrict__ bias,
                                                   float* __restrict__ out, int M) {
    __shared__ float As[BK][BM];   // transposed: As[k][m]
    __shared__ float Bs[BK][BN];

    const int tid = threadIdx.x;
    const int tx = tid & 15;       // N direction
    const int ty = tid >> 4;       // M direction
    const int bm = blockIdx.y * BM;
    const int bn = blockIdx.x * BN;

    // A load: 128 rows x 8 k = 1024 elems, one float4 per thread along k
    const int ar = tid >> 1;             // 0..127
    const int ak = (tid & 1) * 4;        // 0 or 4
    // B load: 8 k x 128 cols = 1024 elems, one float4 per thread along n
    const int br = tid >> 5;             // 0..7
    const int bc = (tid & 31) * 4;       // 0..124

    float acc[8][8];
    #pragma unroll
    for (int i = 0; i < 8; i++)
        #pragma unroll
        for (int j = 0; j < 8; j++) acc[i][j] = 0.0f;

    for (int k0 = 0; k0 < IN_CH; k0 += BK) {
        const int grow = bm + ar;
        float4 av = (grow < M) ? *(const float4*)&g_y[(size_t)grow * IN_CH + k0 + ak]
                               : make_float4(0.f, 0.f, 0.f, 0.f);
        As[ak + 0][ar] = av.x;
        As[ak + 1][ar] = av.y;
        As[ak + 2][ar] = av.z;
        As[ak + 3][ar] = av.w;

        *(float4*)&Bs[br][bc] = *(const float4*)&W[(size_t)(k0 + br) * OUT_CH + bn + bc];

        __syncthreads();

        #pragma unroll
        for (int k = 0; k < BK; k++) {
            float a[8], b[8];
            *(float4*)&a[0] = *(const float4*)&As[k][ty * 4];
            *(float4*)&a[4] = *(const float4*)&As[k][64 + ty * 4];
            *(float4*)&b[0] = *(const float4*)&Bs[k][tx * 4];
            *(float4*)&b[4] = *(const float4*)&Bs[k][64 + tx * 4];
            #pragma unroll
            for (int i = 0; i < 8; i++)
                #pragma unroll
                for (int j = 0; j < 8; j++)
                    acc[i][j] += a[i] * b[j];
        }
        __syncthreads();
    }

    // Epilogue: add bias, store (guarded on M)
    #pragma unroll
    for (int half = 0; half < 2; half++) {
        const int cbase = bn + half * 64 + tx * 4;
        float4 bv = *(const float4*)&bias[cbase];
        #pragma unroll
        for (int i = 0; i < 8; i++) {
            const int grow = bm + (i < 4 ? ty * 4 + i : 64 + ty * 4 + (i - 4));
            if (grow < M) {
                float4 v;
                v.x = acc[i][half * 4 + 0] + bv.x;
                v.y = acc[i][half * 4 + 1] + bv.y;
                v.z = acc[i][half * 4 + 2] + bv.z;
                v.w = acc[i][half * 4 + 3] + bv.w;
                *(float4*)&out[(size_t)grow * OUT_CH + cbase] = v;
            }
        }
    }
}

extern "C" void kernel_launch(void* const* d_in, const int* in_sizes, int n_in,
                              void* d_out, int out_size) {
    const float* x   = (const float*)d_in[0];      // [N,128]
    const float* W   = (const float*)d_in[1];      // [128,256]
    const float* b   = (const float*)d_in[2];      // [256]
    const void*  ei  = d_in[3];                    // [2,E] int64 OR int32
    const float* ew  = (const float*)d_in[4];      // [E]

    const int N = in_sizes[0] / IN_CH;
    const int E = in_sizes[4];
    float* out = (float*)d_out;

    detect_kernel<<<1, 256>>>((const int*)ei);

    deg_init_kernel<<<(N + 255) / 256, 256>>>(N);
    deg_accum_kernel<<<(E + 255) / 256, 256>>>(ei, ew, E);
    dinv_kernel<<<(N + 255) / 256, 256>>>(N);

    const int initv = N * (IN_CH / 4);
    agg_init_kernel<<<(initv + 255) / 256, 256>>>(x, N);

    const long long nthreads = (long long)E * 32;
    agg_scatter_kernel<<<(unsigned)((nthreads + 255) / 256), 256>>>(ei, ew, x, E);

    dim3 ggrid(OUT_CH / BN, (N + BM - 1) / BM);
    gemm_kernel<<<ggrid, 256>>>(W, b, out, N);
}

// round 4
// speedup vs baseline: 1.8561x; 1.2186x over previous
#include <cuda_runtime.h>
#include <cuda_bf16.h>
#include <cstdint>

#define N_NODES 50000
#define E_EDGES 500000
#define IN_CH   128
#define OUT_CH  256
#define M_PAD   50048   // 391 * 128

// Scratch (allocation-free rule: __device__ globals)
__device__ __align__(16) float g_deg[N_NODES];
__device__ __align__(16) float g_dinv[N_NODES];
__device__ __align__(16) float g_y[(size_t)N_NODES * IN_CH];
__device__ __align__(16) __nv_bfloat16 g_ybf[(size_t)M_PAD * 256];   // [yh(128) | yl(128)] per row
__device__ __align__(16) __nv_bfloat16 g_Wsplit[384 * 256];          // [Wh; Wl; Wh]
__device__ int g_is64;

__device__ __forceinline__ float sigmoidf_(float v) {
    return 1.0f / (1.0f + __expf(-v));
}

__device__ __forceinline__ int load_idx(const void* ei, int E, int which, int e) {
    if (g_is64) return (int)((const long long*)ei)[(size_t)which * E + e];
    else        return ((const int*)ei)[which * E + e];
}

// k0: deg=1 everywhere; block 0 additionally detects edge_index dtype
// (int64 node ids < 2^31 -> all odd int32 words zero).
__global__ void init_detect_kernel(const int* __restrict__ ei32, int n) {
    int i = blockIdx.x * blockDim.x + threadIdx.x;
    if (i < n) g_deg[i] = 1.0f;
    if (blockIdx.x == 0) {
        __shared__ int any;
        if (threadIdx.x == 0) any = 0;
        __syncthreads();
        int nz = 0;
        for (int j = threadIdx.x; j < 1024; j += blockDim.x)
            if (ei32[2 * j + 1] != 0) nz = 1;
        if (nz) any = 1;       // benign race
        __syncthreads();
        if (threadIdx.x == 0) g_is64 = any ? 0 : 1;
    }
}

// k1: deg[col] += sigmoid(ew)
__global__ void deg_accum_kernel(const void* __restrict__ ei,
                                 const float* __restrict__ ew, int E) {
    int e = blockIdx.x * blockDim.x + threadIdx.x;
    if (e < E) {
        int c = load_idx(ei, E, 1, e);
        atomicAdd(&g_deg[c], sigmoidf_(ew[e]));
    }
}

// k2: warp per node: dinv = rsqrt(deg); y = x * dinv^2 (self-loop term)
__global__ void agg_init_kernel(const float* __restrict__ x, int n) {
    int gid = blockIdx.x * blockDim.x + threadIdx.x;
    int node = gid >> 5, lane = gid & 31;
    if (node >= n) return;
    float d = rsqrtf(g_deg[node]);
    if (lane == 0) g_dinv[node] = d;
    float d2 = d * d;
    float4 v = ((const float4*)(x + (size_t)node * IN_CH))[lane];
    v.x *= d2; v.y *= d2; v.z *= d2; v.w *= d2;
    ((float4*)(g_y + (size_t)node * IN_CH))[lane] = v;
}

// k3: warp per edge: y[col] += x[row] * (dinv[row]*sigmoid(w)*dinv[col])
__global__ __launch_bounds__(256) void agg_scatter_kernel(const void* __restrict__ ei,
                                                          const float* __restrict__ ew,
                                                          const float* __restrict__ x, int E) {
    const int gid = blockIdx.x * blockDim.x + threadIdx.x;
    const int e = gid >> 5;
    const int lane = gid & 31;
    if (e >= E) return;

    const int r = load_idx(ei, E, 0, e);
    const int c = load_idx(ei, E, 1, e);
    const float norm = g_dinv[r] * sigmoidf_(ew[e]) * g_dinv[c];

    float4 v = ((const float4*)(x + (size_t)r * IN_CH))[lane];
    v.x *= norm; v.y *= norm; v.z *= norm; v.w *= norm;
    float* addr = g_y + (size_t)c * IN_CH + lane * 4;
    asm volatile("red.global.add.v4.f32 [%0], {%1, %2, %3, %4};"
                 :: "l"(addr), "f"(v.x), "f"(v.y), "f"(v.z), "f"(v.w)
                 : "memory");
}

// k4: W -> [Wh; Wl; Wh] bf16 split (3-term product needs Wh twice)
__global__ void wsplit_kernel(const float* __restrict__ W) {
    int i = blockIdx.x * blockDim.x + threadIdx.x;
    if (i < IN_CH * OUT_CH) {
        float w = W[i];
        __nv_bfloat16 hi = __float2bfloat16(w);
        __nv_bfloat16 lo = __float2bfloat16(w - __bfloat162float(hi));
        g_Wsplit[i] = hi;
        g_Wsplit[IN_CH * OUT_CH + i] = lo;
        g_Wsplit[2 * IN_CH * OUT_CH + i] = hi;
    }
}

// k5: warp per (padded) node: y -> ybf = [bf16 hi | bf16 residual]
__global__ void convert_kernel(int n) {
    int gid = blockIdx.x * blockDim.x + threadIdx.x;
    int node = gid >> 5, lane = gid & 31;
    if (node >= M_PAD) return;
    float4 v = make_float4(0.f, 0.f, 0.f, 0.f);
    if (node < n) v = ((const float4*)(g_y + (size_t)node * IN_CH))[lane];
    __nv_bfloat162 h01 = __floats2bfloat162_rn(v.x, v.y);
    __nv_bfloat162 h23 = __floats2bfloat162_rn(v.z, v.w);
    __nv_bfloat162 l01 = __floats2bfloat162_rn(v.x - __low2float(h01), v.y - __high2float(h01));
    __nv_bfloat162 l23 = __floats2bfloat162_rn(v.z - __low2float(h23), v.w - __high2float(h23));
    __nv_bfloat16* base = g_ybf + (size_t)node * 256 + lane * 4;
    *(__nv_bfloat162*)(base + 0) = h01;
    *(__nv_bfloat162*)(base + 2) = h23;
    *(__nv_bfloat162*)(base + 128) = l01;
    *(__nv_bfloat162*)(base + 130) = l23;
}

// k6: bf16 tensor-core GEMM  out[M,256] = A'[M,384] @ B'[384,256] + bias
// A' = [yh | yh | yl] (yh block consumed twice), B' = [Wh; Wl; Wh].
// Block 128x128, 8 warps (4 M x 2 N), warp tile 32x64, k-step 16, 24 steps.
#define AS_STRIDE 24    // bf16 elems per As row (16 data + 8 pad -> 48B, conflict-free)
#define BS_STRIDE 136   // bf16 elems per Bs row (128 data + 8 pad -> 272B, conflict-free)

__device__ __forceinline__ int a_col_off(int ks) {
    // column offset into ybf's 256-wide [yh|yl] layout for k-step ks
    return (ks < 8) ? ks * 16 : (ks < 16) ? (ks - 8) * 16 : 128 + (ks - 16) * 16;
}

#define MMA16816(D, A, B0, B1)                                                 \
    asm volatile("mma.sync.aligned.m16n8k16.row.col.f32.bf16.bf16.f32 "        \
                 "{%0,%1,%2,%3}, {%4,%5,%6,%7}, {%8,%9}, {%0,%1,%2,%3};"       \
                 : "+f"(D[0]), "+f"(D[1]), "+f"(D[2]), "+f"(D[3])              \
                 : "r"(A[0]), "r"(A[1]), "r"(A[2]), "r"(A[3]), "r"(B0), "r"(B1))

__global__ __launch_bounds__(256) void gemm_bf16_kernel(const float* __restrict__ bias,
                                                        float* __restrict__ out, int M) {
    __shared__ __align__(16) __nv_bfloat16 As[128 * AS_STRIDE];
    __shared__ __align__(16) __nv_bfloat16 Bs[16 * BS_STRIDE];

    const int tid = threadIdx.x;
    const int wid = tid >> 5, lane = tid & 31;
    const int wm = (wid & 3) * 32;    // warp M offset in block
    const int wn = (wid >> 2) * 64;   // warp N offset in block
    const int bm = blockIdx.y * 128;
    const int bn = blockIdx.x * 128;

    // gmem->smem mapping
    const int a_row = tid >> 1, a_half = tid & 1;   // 128 rows x 2 halves of 16B
    const int b_row = tid >> 4, b_seg = tid & 15;   // 16 rows x 16 segs of 16B

    // ldmatrix smem addresses
    const uint32_t as_u32 = (uint32_t)__cvta_generic_to_shared(As);
    const uint32_t bs_u32 = (uint32_t)__cvta_generic_to_shared(Bs);
    const int l15 = lane & 15, lhi = lane >> 4;
    // A frag (per mi): rows wm+mi*16+l15, 16B chunk lhi
    const uint32_t a_lm0 = as_u32 + (uint32_t)(wm + l15) * (AS_STRIDE * 2) + lhi * 16;
    // B frag (per ng): k row l15, n col wn+ng*16+lhi*8
    const uint32_t b_lm_base = bs_u32 + (uint32_t)l15 * (BS_STRIDE * 2) + (uint32_t)(wn + lhi * 8) * 2;

    float d[2][8][4];
    #pragma unroll
    for (int mi = 0; mi < 2; mi++)
        #pragma unroll
        for (int nf = 0; nf < 8; nf++)
            #pragma unroll
            for (int j = 0; j < 4; j++) d[mi][nf][j] = 0.0f;

    // prologue: stage 0 into registers
    uint4 a_reg = *(const uint4*)&g_ybf[(size_t)(bm + a_row) * 256 + a_col_off(0) + a_half * 8];
    uint4 b_reg = *(const uint4*)&g_Wsplit[(size_t)(0 * 16 + b_row) * 256 + bn + b_seg * 8];

    for (int ks = 0; ks < 24; ks++) {
        __syncthreads();
        *(uint4*)&As[a_row * AS_STRIDE + a_half * 8] = a_reg;
        *(uint4*)&Bs[b_row * BS_STRIDE + b_seg * 8] = b_reg;
        __syncthreads();

        if (ks + 1 < 24) {
            a_reg = *(const uint4*)&g_ybf[(size_t)(bm + a_row) * 256 + a_col_off(ks + 1) + a_half * 8];
            b_reg = *(const uint4*)&g_Wsplit[(size_t)((ks + 1) * 16 + b_row) * 256 + bn + b_seg * 8];
        }

        uint32_t a[2][4];
        #pragma unroll
        for (int mi = 0; mi < 2; mi++) {
            uint32_t addr = a_lm0 + (uint32_t)(mi * 16) * (AS_STRIDE * 2);
            asm volatile("ldmatrix.sync.aligned.m8n8.x4.shared.b16 {%0,%1,%2,%3}, [%4];"
                         : "=r"(a[mi][0]), "=r"(a[mi][1]), "=r"(a[mi][2]), "=r"(a[mi][3])
                         : "r"(addr));
        }

        #pragma unroll
        for (int ng = 0; ng < 4; ng++) {
            uint32_t b0, b1, b2, b3;
            uint32_t addr = b_lm_base + (uint32_t)(ng * 16) * 2;
            asm volatile("ldmatrix.sync.aligned.m8n8.x4.trans.shared.b16 {%0,%1,%2,%3}, [%4];"
                         : "=r"(b0), "=r"(b1), "=r"(b2), "=r"(b3)
                         : "r"(addr));
            MMA16816(d[0][2 * ng + 0], a[0], b0, b1);
            MMA16816(d[1][2 * ng + 0], a[1], b0, b1);
            MMA16816(d[0][2 * ng + 1], a[0], b2, b3);
            MMA16816(d[1][2 * ng + 1], a[1], b2, b3);
        }
    }

    // epilogue: bias add + fp32 store
    const int l4 = lane >> 2, l2 = 2 * (lane & 3);
    #pragma unroll
    for (int mi = 0; mi < 2; mi++) {
        const int r0 = bm + wm + mi * 16 + l4;
        #pragma unroll
        for (int nf = 0; nf < 8; nf++) {
            const int col = bn + wn + nf * 8 + l2;
            float2 bv = *(const float2*)&bias[col];
            if (r0 < M) {
                float2 s = make_float2(d[mi][nf][0] + bv.x, d[mi][nf][1] + bv.y);
                *(float2*)&out[(size_t)r0 * OUT_CH + col] = s;
            }
            if (r0 + 8 < M) {
                float2 s = make_float2(d[mi][nf][2] + bv.x, d[mi][nf][3] + bv.y);
                *(float2*)&out[(size_t)(r0 + 8) * OUT_CH + col] = s;
            }
        }
    }
}

extern "C" void kernel_launch(void* const* d_in, const int* in_sizes, int n_in,
                              void* d_out, int out_size) {
    const float* x   = (const float*)d_in[0];      // [N,128]
    const float* W   = (const float*)d_in[1];      // [128,256]
    const float* b   = (const float*)d_in[2];      // [256]
    const void*  ei  = d_in[3];                    // [2,E] int64 OR int32
    const float* ew  = (const float*)d_in[4];      // [E]

    const int N = in_sizes[0] / IN_CH;
    const int E = in_sizes[4];
    float* out = (float*)d_out;

    init_detect_kernel<<<(N + 255) / 256, 256>>>((const int*)ei, N);
    deg_accum_kernel<<<(E + 255) / 256, 256>>>(ei, ew, E);

    const long long ithreads = (long long)N * 32;
    agg_init_kernel<<<(unsigned)((ithreads + 255) / 256), 256>>>(x, N);

    const long long sthreads = (long long)E * 32;
    agg_scatter_kernel<<<(unsigned)((sthreads + 255) / 256), 256>>>(ei, ew, x, E);

    wsplit_kernel<<<(IN_CH * OUT_CH + 255) / 256, 256>>>(W);

    const long long cthreads = (long long)M_PAD * 32;
    convert_kernel<<<(unsigned)((cthreads + 255) / 256), 256>>>(N);

    dim3 ggrid(OUT_CH / 128, (M_PAD / 128));
    gemm_bf16_kernel<<<ggrid, 256>>>(b, out, N);
}

// round 5
// speedup vs baseline: 2.5377x; 1.3672x over previous
#include <cuda_runtime.h>
#include <cuda_bf16.h>
#include <cstdint>

#define N_NODES 50000
#define E_EDGES 500000
#define IN_CH   128
#define OUT_CH  256
#define M_PAD   50048   // 391 * 128
#define SCAN_BLOCKS ((N_NODES + 255) / 256)   // 196

// Scratch (allocation-free rule: __device__ globals)
__device__ __align__(16) float g_dinv[N_NODES];
__device__ int   g_count[N_NODES];
__device__ int   g_rowptr[N_NODES];
__device__ int   g_cursor[N_NODES];
__device__ int   g_bsum[256];
__device__ int   g_boff[256];
__device__ __align__(16) int2  g_edge[E_EDGES];                     // {src, bits(sigmoid(w))}
__device__ __align__(16) __nv_bfloat16 g_ybf[(size_t)M_PAD * 256];  // [yh(128) | yl(128)] per row
__device__ __align__(16) __nv_bfloat16 g_Wsplit[384 * 256];         // [Wh; Wl; Wh]
__device__ int g_is64;

__device__ __forceinline__ float sigmoidf_(float v) {
    return 1.0f / (1.0f + __expf(-v));
}

__device__ __forceinline__ int load_idx(const void* ei, int E, int which, int e) {
    if (g_is64) return (int)((const long long*)ei)[(size_t)which * E + e];
    else        return ((const int*)ei)[which * E + e];
}

// k0: count=0 everywhere; block 0 detects edge_index dtype
// (int64 node ids < 2^31 -> all odd int32 words zero).
__global__ void init_detect_kernel(const int* __restrict__ ei32, int n) {
    int i = blockIdx.x * blockDim.x + threadIdx.x;
    if (i < n) g_count[i] = 0;
    if (blockIdx.x == 0) {
        __shared__ int any;
        if (threadIdx.x == 0) any = 0;
        __syncthreads();
        int nz = 0;
        for (int j = threadIdx.x; j < 1024; j += blockDim.x)
            if (ei32[2 * j + 1] != 0) nz = 1;
        if (nz) any = 1;       // benign race
        __syncthreads();
        if (threadIdx.x == 0) g_is64 = any ? 0 : 1;
    }
}

// k1: count[col]++
__global__ void count_kernel(const void* __restrict__ ei, int E) {
    int e = blockIdx.x * blockDim.x + threadIdx.x;
    if (e < E) atomicAdd(&g_count[load_idx(ei, E, 1, e)], 1);
}

// k2a: per-block exclusive scan of counts -> rowptr (local), block sums -> bsum
__global__ void scanA_kernel(int n) {
    __shared__ int s[256];
    int i = blockIdx.x * 256 + threadIdx.x;
    int v = (i < n) ? g_count[i] : 0;
    s[threadIdx.x] = v;
    __syncthreads();
    #pragma unroll
    for (int off = 1; off < 256; off <<= 1) {
        int t = (threadIdx.x >= off) ? s[threadIdx.x - off] : 0;
        __syncthreads();
        s[threadIdx.x] += t;
        __syncthreads();
    }
    if (i < n) g_rowptr[i] = s[threadIdx.x] - v;          // exclusive
    if (threadIdx.x == 255) g_bsum[blockIdx.x] = s[255];  // inclusive total
}

// k2b: single-block exclusive scan of the block sums
__global__ void scanB_kernel(int nb) {
    __shared__ int s[256];
    int v = (threadIdx.x < nb) ? g_bsum[threadIdx.x] : 0;
    s[threadIdx.x] = v;
    __syncthreads();
    #pragma unroll
    for (int off = 1; off < 256; off <<= 1) {
        int t = (threadIdx.x >= off) ? s[threadIdx.x - off] : 0;
        __syncthreads();
        s[threadIdx.x] += t;
        __syncthreads();
    }
    g_boff[threadIdx.x] = s[threadIdx.x] - v;
}

// k2c: finalize rowptr, init cursor
__global__ void scanC_kernel(int n) {
    int i = blockIdx.x * blockDim.x + threadIdx.x;
    if (i < n) {
        int rp = g_rowptr[i] + g_boff[i >> 8];
        g_rowptr[i] = rp;
        g_cursor[i] = rp;
    }
}

// k3: place edges into CSR buckets: {src, sigmoid(w)}
__global__ void place_kernel(const void* __restrict__ ei,
                             const float* __restrict__ ew, int E) {
    int e = blockIdx.x * blockDim.x + threadIdx.x;
    if (e < E) {
        int r = load_idx(ei, E, 0, e);
        int c = load_idx(ei, E, 1, e);
        float w = sigmoidf_(ew[e]);
        int pos = atomicAdd(&g_cursor[c], 1);
        g_edge[pos] = make_int2(r, __float_as_int(w));
    }
}

// k4: deg = 1 + sum(w) over CSR; dinv = rsqrt(deg). Thread per node.
__global__ void dinv_kernel(int n) {
    int i = blockIdx.x * blockDim.x + threadIdx.x;
    if (i >= n) return;
    int start = g_rowptr[i], cnt = g_count[i];
    float deg = 1.0f;
    for (int e = start; e < start + cnt; e++)
        deg += __int_as_float(g_edge[e].y);
    g_dinv[i] = rsqrtf(deg);
}

// k5: warp per node: register-accumulated aggregation + bf16 hi/lo convert.
// acc = x[node]*dinv^2 + sum_e x[src]*(dinv*w*dinv[src]);  g_ybf = split(acc)
__global__ __launch_bounds__(256) void gather_kernel(const float* __restrict__ x, int n) {
    const int gid = blockIdx.x * blockDim.x + threadIdx.x;
    const int node = gid >> 5, lane = gid & 31;
    if (node >= M_PAD) return;

    float4 acc = make_float4(0.f, 0.f, 0.f, 0.f);
    if (node < n) {
        const float d = g_dinv[node];
        const float d2 = d * d;
        float4 xv = __ldg(&((const float4*)(x + (size_t)node * IN_CH))[lane]);
        acc.x = xv.x * d2; acc.y = xv.y * d2; acc.z = xv.z * d2; acc.w = xv.w * d2;

        const int start = g_rowptr[node];
        const int end = start + g_count[node];
        for (int e = start; e < end; e++) {
            int2 ed = g_edge[e];                       // broadcast load
            const int r = ed.x;
            const float nm = d * __int_as_float(ed.y) * g_dinv[r];
            float4 v = __ldg(&((const float4*)(x + (size_t)r * IN_CH))[lane]);
            acc.x += v.x * nm; acc.y += v.y * nm; acc.z += v.z * nm; acc.w += v.w * nm;
        }
    }

    // bf16 hi/lo split, fused (was convert_kernel)
    __nv_bfloat162 h01 = __floats2bfloat162_rn(acc.x, acc.y);
    __nv_bfloat162 h23 = __floats2bfloat162_rn(acc.z, acc.w);
    __nv_bfloat162 l01 = __floats2bfloat162_rn(acc.x - __low2float(h01), acc.y - __high2float(h01));
    __nv_bfloat162 l23 = __floats2bfloat162_rn(acc.z - __low2float(h23), acc.w - __high2float(h23));
    __nv_bfloat16* base = g_ybf + (size_t)node * 256 + lane * 4;
    *(__nv_bfloat162*)(base + 0) = h01;
    *(__nv_bfloat162*)(base + 2) = h23;
    *(__nv_bfloat162*)(base + 128) = l01;
    *(__nv_bfloat162*)(base + 130) = l23;
}

// k6: W -> [Wh; Wl; Wh] bf16 split
__global__ void wsplit_kernel(const float* __restrict__ W) {
    int i = blockIdx.x * blockDim.x + threadIdx.x;
    if (i < IN_CH * OUT_CH) {
        float w = W[i];
        __nv_bfloat16 hi = __float2bfloat16(w);
        __nv_bfloat16 lo = __float2bfloat16(w - __bfloat162float(hi));
        g_Wsplit[i] = hi;
        g_Wsplit[IN_CH * OUT_CH + i] = lo;
        g_Wsplit[2 * IN_CH * OUT_CH + i] = hi;
    }
}

// k7: bf16 tensor-core GEMM  out[M,256] = A'[M,384] @ B'[384,256] + bias
// A' = [yh | yh | yl], B' = [Wh; Wl; Wh].
// Block 128x128, 8 warps (4 M x 2 N), warp tile 32x64, k-step 16, 24 steps.
#define AS_STRIDE 24    // 16 data + 8 pad bf16 -> 48B rows, conflict-free
#define BS_STRIDE 136   // 128 data + 8 pad bf16 -> 272B rows, conflict-free

__device__ __forceinline__ int a_col_off(int ks) {
    return (ks < 8) ? ks * 16 : (ks < 16) ? (ks - 8) * 16 : 128 + (ks - 16) * 16;
}

#define MMA16816(D, A, B0, B1)                                                 \
    asm volatile("mma.sync.aligned.m16n8k16.row.col.f32.bf16.bf16.f32 "        \
                 "{%0,%1,%2,%3}, {%4,%5,%6,%7}, {%8,%9}, {%0,%1,%2,%3};"       \
                 : "+f"(D[0]), "+f"(D[1]), "+f"(D[2]), "+f"(D[3])              \
                 : "r"(A[0]), "r"(A[1]), "r"(A[2]), "r"(A[3]), "r"(B0), "r"(B1))

__global__ __launch_bounds__(256) void gemm_bf16_kernel(const float* __restrict__ bias,
                                                        float* __restrict__ out, int M) {
    __shared__ __align__(16) __nv_bfloat16 As[128 * AS_STRIDE];
    __shared__ __align__(16) __nv_bfloat16 Bs[16 * BS_STRIDE];

    const int tid = threadIdx.x;
    const int wid = tid >> 5, lane = tid & 31;
    const int wm = (wid & 3) * 32;
    const int wn = (wid >> 2) * 64;
    const int bm = blockIdx.y * 128;
    const int bn = blockIdx.x * 128;

    const int a_row = tid >> 1, a_half = tid & 1;
    const int b_row = tid >> 4, b_seg = tid & 15;

    const uint32_t as_u32 = (uint32_t)__cvta_generic_to_shared(As);
    const uint32_t bs_u32 = (uint32_t)__cvta_generic_to_shared(Bs);
    const int l15 = lane & 15, lhi = lane >> 4;
    const uint32_t a_lm0 = as_u32 + (uint32_t)(wm + l15) * (AS_STRIDE * 2) + lhi * 16;
    const uint32_t b_lm_base = bs_u32 + (uint32_t)l15 * (BS_STRIDE * 2) + (uint32_t)(wn + lhi * 8) * 2;

    float d[2][8][4];
    #pragma unroll
    for (int mi = 0; mi < 2; mi++)
        #pragma unroll
        for (int nf = 0; nf < 8; nf++)
            #pragma unroll
            for (int j = 0; j < 4; j++) d[mi][nf][j] = 0.0f;

    uint4 a_reg = *(const uint4*)&g_ybf[(size_t)(bm + a_row) * 256 + a_col_off(0) + a_half * 8];
    uint4 b_reg = *(const uint4*)&g_Wsplit[(size_t)(0 * 16 + b_row) * 256 + bn + b_seg * 8];

    for (int ks = 0; ks < 24; ks++) {
        __syncthreads();
        *(uint4*)&As[a_row * AS_STRIDE + a_half * 8] = a_reg;
        *(uint4*)&Bs[b_row * BS_STRIDE + b_seg * 8] = b_reg;
        __syncthreads();

        if (ks + 1 < 24) {
            a_reg = *(const uint4*)&g_ybf[(size_t)(bm + a_row) * 256 + a_col_off(ks + 1) + a_half * 8];
            b_reg = *(const uint4*)&g_Wsplit[(size_t)((ks + 1) * 16 + b_row) * 256 + bn + b_seg * 8];
        }

        uint32_t a[2][4];
        #pragma unroll
        for (int mi = 0; mi < 2; mi++) {
            uint32_t addr = a_lm0 + (uint32_t)(mi * 16) * (AS_STRIDE * 2);
            asm volatile("ldmatrix.sync.aligned.m8n8.x4.shared.b16 {%0,%1,%2,%3}, [%4];"
                         : "=r"(a[mi][0]), "=r"(a[mi][1]), "=r"(a[mi][2]), "=r"(a[mi][3])
                         : "r"(addr));
        }

        #pragma unroll
        for (int ng = 0; ng < 4; ng++) {
            uint32_t b0, b1, b2, b3;
            uint32_t addr = b_lm_base + (uint32_t)(ng * 16) * 2;
            asm volatile("ldmatrix.sync.aligned.m8n8.x4.trans.shared.b16 {%0,%1,%2,%3}, [%4];"
                         : "=r"(b0), "=r"(b1), "=r"(b2), "=r"(b3)
                         : "r"(addr));
            MMA16816(d[0][2 * ng + 0], a[0], b0, b1);
            MMA16816(d[1][2 * ng + 0], a[1], b0, b1);
            MMA16816(d[0][2 * ng + 1], a[0], b2, b3);
            MMA16816(d[1][2 * ng + 1], a[1], b2, b3);
        }
    }

    const int l4 = lane >> 2, l2 = 2 * (lane & 3);
    #pragma unroll
    for (int mi = 0; mi < 2; mi++) {
        const int r0 = bm + wm + mi * 16 + l4;
        #pragma unroll
        for (int nf = 0; nf < 8; nf++) {
            const int col = bn + wn + nf * 8 + l2;
            float2 bv = *(const float2*)&bias[col];
            if (r0 < M) {
                float2 s = make_float2(d[mi][nf][0] + bv.x, d[mi][nf][1] + bv.y);
                *(float2*)&out[(size_t)r0 * OUT_CH + col] = s;
            }
            if (r0 + 8 < M) {
                float2 s = make_float2(d[mi][nf][2] + bv.x, d[mi][nf][3] + bv.y);
                *(float2*)&out[(size_t)(r0 + 8) * OUT_CH + col] = s;
            }
        }
    }
}

extern "C" void kernel_launch(void* const* d_in, const int* in_sizes, int n_in,
                              void* d_out, int out_size) {
    const float* x   = (const float*)d_in[0];      // [N,128]
    const float* W   = (const float*)d_in[1];      // [128,256]
    const float* b   = (const float*)d_in[2];      // [256]
    const void*  ei  = d_in[3];                    // [2,E] int64 OR int32
    const float* ew  = (const float*)d_in[4];      // [E]

    const int N = in_sizes[0] / IN_CH;
    const int E = in_sizes[4];
    float* out = (float*)d_out;

    const int nblocks = (N + 255) / 256;

    init_detect_kernel<<<nblocks, 256>>>((const int*)ei, N);
    count_kernel<<<(E + 255) / 256, 256>>>(ei, E);
    scanA_kernel<<<nblocks, 256>>>(N);
    scanB_kernel<<<1, 256>>>(nblocks);
    scanC_kernel<<<nblocks, 256>>>(N);
    place_kernel<<<(E + 255) / 256, 256>>>(ei, ew, E);
    dinv_kernel<<<nblocks, 256>>>(N);

    const long long gthreads = (long long)M_PAD * 32;
    gather_kernel<<<(unsigned)((gthreads + 255) / 256), 256>>>(x, N);

    wsplit_kernel<<<(IN_CH * OUT_CH + 255) / 256, 256>>>(W);

    dim3 ggrid(OUT_CH / 128, M_PAD / 128);
    gemm_bf16_kernel<<<ggrid, 256>>>(b, out, N);
}

// round 6
// speedup vs baseline: 2.6341x; 1.0380x over previous
#include <cuda_runtime.h>
#include <cuda_bf16.h>
#include <cstdint>

#define N_NODES 50000
#define E_EDGES 500000
#define IN_CH   128
#define OUT_CH  256
#define M_PAD   50048   // 391 * 128

// Scratch (allocation-free rule: __device__ globals)
__device__ __align__(16) float g_dinv[N_NODES];
__device__ __align__(16) float g_degf[N_NODES];
__device__ int   g_count[N_NODES];
__device__ int   g_rowptr[N_NODES];
__device__ int   g_cursor[N_NODES];
__device__ int   g_bsum[256];
__device__ int   g_boff[256];
__device__ __align__(16) int2  g_edge[E_EDGES];                     // {src, bits(sigmoid(w))}
__device__ __align__(16) __nv_bfloat16 g_ybf[(size_t)M_PAD * 256];  // [yh(128) | yl(128)] per row
__device__ __align__(16) __nv_bfloat16 g_Wsplit[384 * 256];         // [Wh; Wl; Wh]
__device__ int g_is64;

__device__ __forceinline__ float sigmoidf_(float v) {
    return 1.0f / (1.0f + __expf(-v));
}

__device__ __forceinline__ int load_idx(const void* ei, int E, int which, int e) {
    if (g_is64) return (int)((const long long*)ei)[(size_t)which * E + e];
    else        return ((const int*)ei)[which * E + e];
}

// k0: count=0, degf=1 everywhere; also W -> [Wh; Wl; Wh] bf16 split;
// block 0 detects edge_index dtype (int64 ids < 2^31 -> odd int32 words zero).
__global__ void init_kernel(const int* __restrict__ ei32, const float* __restrict__ W, int n) {
    int i = blockIdx.x * blockDim.x + threadIdx.x;
    if (i < n) { g_count[i] = 0; g_degf[i] = 1.0f; }
    if (i < IN_CH * OUT_CH) {
        float w = W[i];
        __nv_bfloat16 hi = __float2bfloat16(w);
        __nv_bfloat16 lo = __float2bfloat16(w - __bfloat162float(hi));
        g_Wsplit[i] = hi;
        g_Wsplit[IN_CH * OUT_CH + i] = lo;
        g_Wsplit[2 * IN_CH * OUT_CH + i] = hi;
    }
    if (blockIdx.x == 0) {
        __shared__ int any;
        if (threadIdx.x == 0) any = 0;
        __syncthreads();
        int nz = 0;
        for (int j = threadIdx.x; j < 1024; j += blockDim.x)
            if (ei32[2 * j + 1] != 0) nz = 1;
        if (nz) any = 1;       // benign race
        __syncthreads();
        if (threadIdx.x == 0) g_is64 = any ? 0 : 1;
    }
}

// k1: count[col]++ and degf[col] += sigmoid(ew)  (fused)
__global__ void count_kernel(const void* __restrict__ ei,
                             const float* __restrict__ ew, int E) {
    int e = blockIdx.x * blockDim.x + threadIdx.x;
    if (e < E) {
        int c = load_idx(ei, E, 1, e);
        atomicAdd(&g_count[c], 1);
        atomicAdd(&g_degf[c], sigmoidf_(ew[e]));
    }
}

// k2a: per-block exclusive scan of counts -> rowptr(local), block sums -> bsum;
// fused: dinv = rsqrt(degf)
__global__ void scanA_kernel(int n) {
    __shared__ int s[256];
    int i = blockIdx.x * 256 + threadIdx.x;
    int v = (i < n) ? g_count[i] : 0;
    if (i < n) g_dinv[i] = rsqrtf(g_degf[i]);
    s[threadIdx.x] = v;
    __syncthreads();
    #pragma unroll
    for (int off = 1; off < 256; off <<= 1) {
        int t = (threadIdx.x >= off) ? s[threadIdx.x - off] : 0;
        __syncthreads();
        s[threadIdx.x] += t;
        __syncthreads();
    }
    if (i < n) g_rowptr[i] = s[threadIdx.x] - v;          // exclusive
    if (threadIdx.x == 255) g_bsum[blockIdx.x] = s[255];  // inclusive total
}

// k2b: single-block exclusive scan of the block sums
__global__ void scanB_kernel(int nb) {
    __shared__ int s[256];
    int v = (threadIdx.x < nb) ? g_bsum[threadIdx.x] : 0;
    s[threadIdx.x] = v;
    __syncthreads();
    #pragma unroll
    for (int off = 1; off < 256; off <<= 1) {
        int t = (threadIdx.x >= off) ? s[threadIdx.x - off] : 0;
        __syncthreads();
        s[threadIdx.x] += t;
        __syncthreads();
    }
    g_boff[threadIdx.x] = s[threadIdx.x] - v;
}

// k2c: finalize rowptr, init cursor
__global__ void scanC_kernel(int n) {
    int i = blockIdx.x * blockDim.x + threadIdx.x;
    if (i < n) {
        int rp = g_rowptr[i] + g_boff[i >> 8];
        g_rowptr[i] = rp;
        g_cursor[i] = rp;
    }
}

// k3: place edges into CSR buckets: {src, sigmoid(w)}
__global__ void place_kernel(const void* __restrict__ ei,
                             const float* __restrict__ ew, int E) {
    int e = blockIdx.x * blockDim.x + threadIdx.x;
    if (e < E) {
        int r = load_idx(ei, E, 0, e);
        int c = load_idx(ei, E, 1, e);
        float w = sigmoidf_(ew[e]);
        int pos = atomicAdd(&g_cursor[c], 1);
        g_edge[pos] = make_int2(r, __float_as_int(w));
    }
}

// k4: warp per node: register-accumulated aggregation + bf16 hi/lo convert.
// acc = x[node]*dinv^2 + sum_e x[src]*(dinv*w*dinv[src]);  g_ybf = split(acc)
// 2x unrolled edge loop -> two independent load chains in flight (MLP).
__global__ __launch_bounds__(256) void gather_kernel(const float* __restrict__ x, int n) {
    const int gid = blockIdx.x * blockDim.x + threadIdx.x;
    const int node = gid >> 5, lane = gid & 31;
    if (node >= M_PAD) return;

    float4 acc = make_float4(0.f, 0.f, 0.f, 0.f);
    if (node < n) {
        const float d = g_dinv[node];
        const float d2 = d * d;
        float4 xv = __ldg(&((const float4*)(x + (size_t)node * IN_CH))[lane]);
        acc.x = xv.x * d2; acc.y = xv.y * d2; acc.z = xv.z * d2; acc.w = xv.w * d2;

        const int start = g_rowptr[node];
        const int end = start + g_count[node];
        int e = start;
        for (; e + 2 <= end; e += 2) {
            int2 ed0 = g_edge[e];
            int2 ed1 = g_edge[e + 1];
            float di0 = g_dinv[ed0.x];
            float di1 = g_dinv[ed1.x];
            float4 v0 = __ldg(&((const float4*)(x + (size_t)ed0.x * IN_CH))[lane]);
            float4 v1 = __ldg(&((const float4*)(x + (size_t)ed1.x * IN_CH))[lane]);
            const float nm0 = d * __int_as_float(ed0.y) * di0;
            const float nm1 = d * __int_as_float(ed1.y) * di1;
            acc.x += v0.x * nm0; acc.y += v0.y * nm0; acc.z += v0.z * nm0; acc.w += v0.w * nm0;
            acc.x += v1.x * nm1; acc.y += v1.y * nm1; acc.z += v1.z * nm1; acc.w += v1.w * nm1;
        }
        if (e < end) {
            int2 ed = g_edge[e];
            const float nm = d * __int_as_float(ed.y) * g_dinv[ed.x];
            float4 v = __ldg(&((const float4*)(x + (size_t)ed.x * IN_CH))[lane]);
            acc.x += v.x * nm; acc.y += v.y * nm; acc.z += v.z * nm; acc.w += v.w * nm;
        }
    }

    // bf16 hi/lo split (fused conversion)
    __nv_bfloat162 h01 = __floats2bfloat162_rn(acc.x, acc.y);
    __nv_bfloat162 h23 = __floats2bfloat162_rn(acc.z, acc.w);
    __nv_bfloat162 l01 = __floats2bfloat162_rn(acc.x - __low2float(h01), acc.y - __high2float(h01));
    __nv_bfloat162 l23 = __floats2bfloat162_rn(acc.z - __low2float(h23), acc.w - __high2float(h23));
    __nv_bfloat16* base = g_ybf + (size_t)node * 256 + lane * 4;
    *(__nv_bfloat162*)(base + 0) = h01;
    *(__nv_bfloat162*)(base + 2) = h23;
    *(__nv_bfloat162*)(base + 128) = l01;
    *(__nv_bfloat162*)(base + 130) = l23;
}

// k5: bf16 tensor-core GEMM  out[M,256] = A'[M,384] @ B'[384,256] + bias
// A' = [yh | yh | yl], B' = [Wh; Wl; Wh].
// Block 128x128, 8 warps (4 M x 2 N), warp tile 32x64, k-step 16, 24 steps.
#define AS_STRIDE 24    // 16 data + 8 pad bf16 -> 48B rows, conflict-free
#define BS_STRIDE 136   // 128 data + 8 pad bf16 -> 272B rows, conflict-free

__device__ __forceinline__ int a_col_off(int ks) {
    return (ks < 8) ? ks * 16 : (ks < 16) ? (ks - 8) * 16 : 128 + (ks - 16) * 16;
}

#define MMA16816(D, A, B0, B1)                                                 \
    asm volatile("mma.sync.aligned.m16n8k16.row.col.f32.bf16.bf16.f32 "        \
                 "{%0,%1,%2,%3}, {%4,%5,%6,%7}, {%8,%9}, {%0,%1,%2,%3};"       \
                 : "+f"(D[0]), "+f"(D[1]), "+f"(D[2]), "+f"(D[3])              \
                 : "r"(A[0]), "r"(A[1]), "r"(A[2]), "r"(A[3]), "r"(B0), "r"(B1))

__global__ __launch_bounds__(256) void gemm_bf16_kernel(const float* __restrict__ bias,
                                                        float* __restrict__ out, int M) {
    __shared__ __align__(16) __nv_bfloat16 As[128 * AS_STRIDE];
    __shared__ __align__(16) __nv_bfloat16 Bs[16 * BS_STRIDE];

    const int tid = threadIdx.x;
    const int wid = tid >> 5, lane = tid & 31;
    const int wm = (wid & 3) * 32;
    const int wn = (wid >> 2) * 64;
    const int bm = blockIdx.y * 128;
    const int bn = blockIdx.x * 128;

    const int a_row = tid >> 1, a_half = tid & 1;
    const int b_row = tid >> 4, b_seg = tid & 15;

    const uint32_t as_u32 = (uint32_t)__cvta_generic_to_shared(As);
    const uint32_t bs_u32 = (uint32_t)__cvta_generic_to_shared(Bs);
    const int l15 = lane & 15, lhi = lane >> 4;
    const uint32_t a_lm0 = as_u32 + (uint32_t)(wm + l15) * (AS_STRIDE * 2) + lhi * 16;
    const uint32_t b_lm_base = bs_u32 + (uint32_t)l15 * (BS_STRIDE * 2) + (uint32_t)(wn + lhi * 8) * 2;

    float d[2][8][4];
    #pragma unroll
    for (int mi = 0; mi < 2; mi++)
        #pragma unroll
        for (int nf = 0; nf < 8; nf++)
            #pragma unroll
            for (int j = 0; j < 4; j++) d[mi][nf][j] = 0.0f;

    uint4 a_reg = *(const uint4*)&g_ybf[(size_t)(bm + a_row) * 256 + a_col_off(0) + a_half * 8];
    uint4 b_reg = *(const uint4*)&g_Wsplit[(size_t)(0 * 16 + b_row) * 256 + bn + b_seg * 8];

    for (int ks = 0; ks < 24; ks++) {
        __syncthreads();
        *(uint4*)&As[a_row * AS_STRIDE + a_half * 8] = a_reg;
        *(uint4*)&Bs[b_row * BS_STRIDE + b_seg * 8] = b_reg;
        __syncthreads();

        if (ks + 1 < 24) {
            a_reg = *(const uint4*)&g_ybf[(size_t)(bm + a_row) * 256 + a_col_off(ks + 1) + a_half * 8];
            b_reg = *(const uint4*)&g_Wsplit[(size_t)((ks + 1) * 16 + b_row) * 256 + bn + b_seg * 8];
        }

        uint32_t a[2][4];
        #pragma unroll
        for (int mi = 0; mi < 2; mi++) {
            uint32_t addr = a_lm0 + (uint32_t)(mi * 16) * (AS_STRIDE * 2);
            asm volatile("ldmatrix.sync.aligned.m8n8.x4.shared.b16 {%0,%1,%2,%3}, [%4];"
                         : "=r"(a[mi][0]), "=r"(a[mi][1]), "=r"(a[mi][2]), "=r"(a[mi][3])
                         : "r"(addr));
        }

        #pragma unroll
        for (int ng = 0; ng < 4; ng++) {
            uint32_t b0, b1, b2, b3;
            uint32_t addr = b_lm_base + (uint32_t)(ng * 16) * 2;
            asm volatile("ldmatrix.sync.aligned.m8n8.x4.trans.shared.b16 {%0,%1,%2,%3}, [%4];"
                         : "=r"(b0), "=r"(b1), "=r"(b2), "=r"(b3)
                         : "r"(addr));
            MMA16816(d[0][2 * ng + 0], a[0], b0, b1);
            MMA16816(d[1][2 * ng + 0], a[1], b0, b1);
            MMA16816(d[0][2 * ng + 1], a[0], b2, b3);
            MMA16816(d[1][2 * ng + 1], a[1], b2, b3);
        }
    }

    const int l4 = lane >> 2, l2 = 2 * (lane & 3);
    #pragma unroll
    for (int mi = 0; mi < 2; mi++) {
        const int r0 = bm + wm + mi * 16 + l4;
        #pragma unroll
        for (int nf = 0; nf < 8; nf++) {
            const int col = bn + wn + nf * 8 + l2;
            float2 bv = *(const float2*)&bias[col];
            if (r0 < M) {
                float2 s = make_float2(d[mi][nf][0] + bv.x, d[mi][nf][1] + bv.y);
                *(float2*)&out[(size_t)r0 * OUT_CH + col] = s;
            }
            if (r0 + 8 < M) {
                float2 s = make_float2(d[mi][nf][2] + bv.x, d[mi][nf][3] + bv.y);
                *(float2*)&out[(size_t)(r0 + 8) * OUT_CH + col] = s;
            }
        }
    }
}

extern "C" void kernel_launch(void* const* d_in, const int* in_sizes, int n_in,
                              void* d_out, int out_size) {
    const float* x   = (const float*)d_in[0];      // [N,128]
    const float* W   = (const float*)d_in[1];      // [128,256]
    const float* b   = (const float*)d_in[2];      // [256]
    const void*  ei  = d_in[3];                    // [2,E] int64 OR int32
    const float* ew  = (const float*)d_in[4];      // [E]

    const int N = in_sizes[0] / IN_CH;
    const int E = in_sizes[4];
    float* out = (float*)d_out;

    const int nblocks = (N + 255) / 256;

    init_kernel<<<nblocks, 256>>>((const int*)ei, W, N);
    count_kernel<<<(E + 255) / 256, 256>>>(ei, ew, E);
    scanA_kernel<<<nblocks, 256>>>(N);
    scanB_kernel<<<1, 256>>>(nblocks);
    scanC_kernel<<<nblocks, 256>>>(N);
    place_kernel<<<(E + 255) / 256, 256>>>(ei, ew, E);

    const long long gthreads = (long long)M_PAD * 32;
    gather_kernel<<<(unsigned)((gthreads + 255) / 256), 256>>>(x, N);

    dim3 ggrid(OUT_CH / 128, M_PAD / 128);
    gemm_bf16_kernel<<<ggrid, 256>>>(b, out, N);
}